// round 5
// baseline (speedup 1.0000x reference)
#include <cuda_runtime.h>
#include <cstddef>

// ---------------------------------------------------------------------------
// Fused 2-block ST-GCN + FC, fp32 with packed f32x2 FMA.
//   x: [64,512,2,21,2]  ->  out: [64,512,2,64]
// Folds (prep): BN into weights; tcn0*gcn_w0 -> tw0f[2ci][3k][32o];
//   tcn1*gcn_w1 -> tw1f[32i][3k][32o] with A-mix moved AFTER tcn1 (commutes);
//   gcn biases -> per-tap constants with t-boundary corrections;
//   fc_w -> zero-padded [64][768] (k' = c*24+v).
// Main: CTA = (chunk of 32 t, hand, batch), 512 thr, lane = channel.
// ---------------------------------------------------------------------------

#define TLEN 512
#define NV   21
#define VP   24
#define NC   32
#define NOUT 64
#define FKP  768
#define TC   32
#define NCHUNK 16
#define SLOTX 36
#define SLOTB 34
#define NWARP 16
#define NTHR  512
#define KC    128
#define KCP   132

// smem float offsets
#define OFF_H1  0
#define SZ_H1   (SLOTB*NC*VP)   // 26112 (reused as hf[32][768] later)
#define OFF_XD  (OFF_H1+SZ_H1)
#define SZ_XD   (SLOTX*2*VP)    // 1728
#define OFF_AX  (OFF_XD+SZ_XD)
#define SZ_AX   (SLOTX*2*VP)    // 1728
#define OFF_AS  (OFF_AX+SZ_AX)
#define SZ_AS   464
#define OFF_TW1 (OFF_AS+SZ_AS)
#define SZ_TW1  (NC*3*NC)       // 3072
#define OFF_FCS (OFF_TW1+SZ_TW1)
#define SZ_FCS  (NOUT*KCP)      // 8448
#define OFF_PP  (OFF_FCS+SZ_FCS)
#define SZ_PP   640
#define SMEM_FLOATS (OFF_PP+SZ_PP)
#define SMEM_BYTES  (SMEM_FLOATS*4)   // ~168.8 KB

// pp layout
#define PP_TW0 0      // 192  [(k*2+ci)*32+o]
#define PP_BK0 192    // 96   [k*32+o]
#define PP_BK1 288    // 96
#define PP_TB0 384    // 32
#define PP_TB1 416    // 32
#define PP_RW  448    // 64   [ci*32+o]
#define PP_RB  512    // 32
#define PP_FCB 544    // 64
#define PP_TOT 608

typedef unsigned long long u64;

__device__ __forceinline__ u64 fma2(u64 a, u64 b, u64 c) {
    u64 d; asm("fma.rn.f32x2 %0,%1,%2,%3;" : "=l"(d) : "l"(a), "l"(b), "l"(c)); return d;
}
__device__ __forceinline__ u64 dup2(float v) {
    u64 r; asm("mov.b64 %0,{%1,%1};" : "=l"(r) : "f"(v)); return r;
}
__device__ __forceinline__ float2 un2(u64 p) {
    float2 f; asm("mov.b64 {%0,%1},%2;" : "=f"(f.x), "=f"(f.y) : "l"(p)); return f;
}

// ------------------------- folded parameter storage -------------------------
__device__ float g_A[SZ_AS];
__device__ float g_tw1f[NC*3*NC];
__device__ float g_fcw2[NOUT*FKP];
__device__ float g_pp[PP_TOT];

__global__ void prep_kernel(
    const float* __restrict__ gcn_w0, const float* __restrict__ gcn_b0,
    const float* __restrict__ tcn_w0, const float* __restrict__ tcn_b0,
    const float* __restrict__ bn_g0,  const float* __restrict__ bn_b0,
    const float* __restrict__ bn_m0,  const float* __restrict__ bn_v0,
    const float* __restrict__ res_w,  const float* __restrict__ res_b,
    const float* __restrict__ res_bn_g, const float* __restrict__ res_bn_b,
    const float* __restrict__ res_bn_m, const float* __restrict__ res_bn_v,
    const float* __restrict__ gcn_w1, const float* __restrict__ gcn_b1,
    const float* __restrict__ tcn_w1, const float* __restrict__ tcn_b1,
    const float* __restrict__ bn_g1,  const float* __restrict__ bn_b1,
    const float* __restrict__ bn_m1,  const float* __restrict__ bn_v1,
    const float* __restrict__ fc_w,   const float* __restrict__ fc_b)
{
    int gtid = blockIdx.x*blockDim.x + threadIdx.x;
    int nthr = gridDim.x*blockDim.x;

    // fc transpose + zero-pad: g_fcw2[j][c*24+v]
    for (int idx = gtid; idx < NOUT*FKP; idx += nthr) {
        int j = idx / FKP, kp = idx - j*FKP;
        int c = kp / VP, v = kp - c*VP;
        g_fcw2[idx] = (v < NV) ? fc_w[j*(NC*NV) + c*NV + v] : 0.f;
    }
    // tw1f[(i*3+k)*32+o] = s1[o] * sum_j tcn_w1[o,j,k] * gcn_w1[j,i]
    for (int idx = gtid; idx < NC*3*NC; idx += nthr) {
        int o = idx & 31, ik = idx >> 5;
        int i = ik / 3, k = ik - i*3;
        float s1 = bn_g1[o] * rsqrtf(bn_v1[o] + 1e-5f);
        float s = 0.f;
        for (int j = 0; j < NC; j++)
            s += tcn_w1[(o*NC + j)*3 + k] * gcn_w1[j*NC + i];
        g_tw1f[(i*3 + k)*NC + o] = s * s1;
    }
    if (gtid == 0) {
        float Ad[NV][NV];
        for (int i = 0; i < NV; i++)
            for (int j = 0; j < NV; j++) Ad[i][j] = (i == j) ? 1.f : 0.f;
        const int conn[20][2] = {{0,1},{1,2},{2,3},{3,4},{0,5},{5,6},{6,7},{7,8},
                                 {0,9},{9,10},{10,11},{11,12},{0,13},{13,14},{14,15},
                                 {15,16},{0,17},{17,18},{18,19},{19,20}};
        for (int e = 0; e < 20; e++) {
            Ad[conn[e][0]][conn[e][1]] = 1.f;
            Ad[conn[e][1]][conn[e][0]] = 1.f;
        }
        float d[NV];
        for (int i = 0; i < NV; i++) {
            float s = 0.f;
            for (int j = 0; j < NV; j++) s += Ad[i][j];
            d[i] = rsqrtf(s);
        }
        for (int i = 0; i < SZ_AS; i++) g_A[i] = 0.f;
        for (int i = 0; i < NV; i++)
            for (int j = 0; j < NV; j++) g_A[i*22 + j] = d[i]*Ad[i][j]*d[j];
    }
    if (gtid < NC) {
        int o = gtid;
        float s0 = bn_g0[o] * rsqrtf(bn_v0[o] + 1e-5f);
        for (int k = 0; k < 3; k++) {
            for (int ci = 0; ci < 2; ci++) {
                float s = 0.f;
                for (int i = 0; i < NC; i++)
                    s += tcn_w0[(o*NC + i)*3 + k] * gcn_w0[i*2 + ci];
                g_pp[PP_TW0 + (k*2 + ci)*NC + o] = s * s0;
            }
            float sb = 0.f;
            for (int i = 0; i < NC; i++)
                sb += tcn_w0[(o*NC + i)*3 + k] * gcn_b0[i];
            g_pp[PP_BK0 + k*NC + o] = sb * s0;

            float sb1 = 0.f;
            float s1 = bn_g1[o] * rsqrtf(bn_v1[o] + 1e-5f);
            for (int j = 0; j < NC; j++)
                sb1 += tcn_w1[(o*NC + j)*3 + k] * gcn_b1[j];
            g_pp[PP_BK1 + k*NC + o] = sb1 * s1;
        }
        g_pp[PP_TB0 + o] = (tcn_b0[o] - bn_m0[o]) * s0 + bn_b0[o];
        float s1 = bn_g1[o] * rsqrtf(bn_v1[o] + 1e-5f);
        g_pp[PP_TB1 + o] = (tcn_b1[o] - bn_m1[o]) * s1 + bn_b1[o];
        float sr = res_bn_g[o] * rsqrtf(res_bn_v[o] + 1e-5f);
        g_pp[PP_RW + o]      = res_w[o*2 + 0] * sr;
        g_pp[PP_RW + NC + o] = res_w[o*2 + 1] * sr;
        g_pp[PP_RB + o] = (res_b[o] - res_bn_m[o]) * sr + res_bn_b[o];
    }
    if (gtid >= 64 && gtid < 128) g_pp[PP_FCB + gtid - 64] = fc_b[gtid - 64];
}

// ------------------------------- main kernel --------------------------------
__global__ __launch_bounds__(NTHR, 1)
void stgcn_kernel(const float* __restrict__ x, float* __restrict__ outp)
{
    extern __shared__ float smem[];
    float* bufH1 = smem + OFF_H1;
    float* bufXd = smem + OFF_XD;
    float* bufAx = smem + OFF_AX;
    float* As    = smem + OFF_AS;
    float* tw1s  = smem + OFF_TW1;
    float* fcs   = smem + OFF_FCS;
    float* pp    = smem + OFF_PP;

    const int tid  = threadIdx.x;
    const int lane = tid & 31;
    const int wid  = tid >> 5;
    const int o    = lane;
    const int t0   = blockIdx.x * TC;
    const int hand = blockIdx.y;
    const int b    = blockIdx.z;

    constexpr int DEG[NV] = {6,3,3,3,2,3,3,3,2,3,3,3,2,3,3,3,2,3,3,3,2};
    constexpr int NBR[NV][6] = {
        {0,1,5,9,13,17},{0,1,2,0,0,0},{1,2,3,0,0,0},{2,3,4,0,0,0},{3,4,0,0,0,0},
        {0,5,6,0,0,0},{5,6,7,0,0,0},{6,7,8,0,0,0},{7,8,0,0,0,0},
        {0,9,10,0,0,0},{9,10,11,0,0,0},{10,11,12,0,0,0},{11,12,0,0,0,0},
        {0,13,14,0,0,0},{13,14,15,0,0,0},{14,15,16,0,0,0},{15,16,0,0,0,0},
        {0,17,18,0,0,0},{17,18,19,0,0,0},{18,19,20,0,0,0},{19,20,0,0,0,0}};

    // ---- prolog: zero x-region, load weights ------------------------------
    {
        float4 z4 = make_float4(0.f, 0.f, 0.f, 0.f);
        float4* zp = (float4*)bufXd;
        for (int i = tid; i < (SZ_XD + SZ_AX)/4; i += NTHR) zp[i] = z4;
        for (int i = tid; i < SZ_AS; i += NTHR)   As[i]   = g_A[i];
        for (int i = tid; i < SZ_TW1; i += NTHR)  tw1s[i] = g_tw1f[i];
        for (int i = tid; i < PP_TOT; i += NTHR)  pp[i]   = g_pp[i];   // FIX: was if(tid<PP_TOT)
    }
    __syncthreads();

    // ---- fill x de-interleaved: bufXd[s][ci*24+v] -------------------------
    for (int idx = tid; idx < SLOTX*NV; idx += NTHR) {
        int s = idx / NV, v = idx - s*NV;
        int t = t0 + s - 2;
        if (t >= 0 && t < TLEN) {
            float2 xv = *(const float2*)(x + (((size_t)(b*TLEN + t)*2 + hand)*NV + v)*2);
            bufXd[s*48 + v]      = xv.x;
            bufXd[s*48 + VP + v] = xv.y;
        }
    }
    __syncthreads();

    // ---- stage A: dense A-mix of 2-ch x -> bufAx [s][ci][24] --------------
    for (int sA = wid; sA < SLOTX; sA += NWARP) {
        if (lane < VP) {
            float s0 = 0.f, s1 = 0.f;
            if (lane < NV) {
                const float* Arow = As + lane*22;
                const float* xr = bufXd + sA*48;
                #pragma unroll
                for (int u = 0; u < NV; u++) {
                    float a = Arow[u];
                    s0 += a * xr[u];
                    s1 += a * xr[VP + u];
                }
            }
            bufAx[sA*48 + lane]      = s0;
            bufAx[sA*48 + VP + lane] = s1;
        }
    }
    __syncthreads();

    // ---- stage B: folded tcn0 + bias + residual + relu -> bufH1 -----------
    {
        const float tb0  = pp[PP_TB0 + o];
        const float bk00 = pp[PP_BK0 + o];
        const float bk01 = pp[PP_BK0 + NC + o];
        const float bk02 = pp[PP_BK0 + 2*NC + o];
        const float rbv  = pp[PP_RB + o];
        const u64 rw0d = dup2(pp[PP_RW + o]);
        const u64 rw1d = dup2(pp[PP_RW + NC + o]);
        for (int sB = wid; sB < SLOTB; sB += NWARP) {
            int t = t0 + sB - 1;
            float* dst = bufH1 + ((size_t)sB*NC + o)*VP;
            if (t < 0 || t >= TLEN) {
                float4 z = make_float4(0.f, 0.f, 0.f, 0.f);
                #pragma unroll
                for (int m = 0; m < 6; m++) ((float4*)dst)[m] = z;
            } else {
                float bias = tb0 + bk00 + bk01 + bk02 + rbv;
                if (t == 0)        bias -= bk00;
                if (t == TLEN - 1) bias -= bk02;
                u64 acc[12];
                u64 bd = dup2(bias);
                #pragma unroll
                for (int q = 0; q < 12; q++) acc[q] = bd;
                #pragma unroll
                for (int k = 0; k < 3; k++) {
                    #pragma unroll
                    for (int ci = 0; ci < 2; ci++) {
                        u64 w = dup2(pp[PP_TW0 + (k*2 + ci)*NC + o]);
                        const ulonglong2* rp = (const ulonglong2*)(bufAx + (sB + k)*48 + ci*VP);
                        #pragma unroll
                        for (int m = 0; m < 6; m++) {
                            ulonglong2 r2 = rp[m];
                            acc[2*m]   = fma2(w, r2.x, acc[2*m]);
                            acc[2*m+1] = fma2(w, r2.y, acc[2*m+1]);
                        }
                    }
                }
                // residual on raw x (rb folded into bias)
                const ulonglong2* x0p = (const ulonglong2*)(bufXd + (sB + 1)*48);
                const ulonglong2* x1p = (const ulonglong2*)(bufXd + (sB + 1)*48 + VP);
                #pragma unroll
                for (int m = 0; m < 6; m++) {
                    ulonglong2 xa = x0p[m], xb = x1p[m];
                    acc[2*m]   = fma2(rw0d, xa.x, acc[2*m]);
                    acc[2*m]   = fma2(rw1d, xb.x, acc[2*m]);
                    acc[2*m+1] = fma2(rw0d, xa.y, acc[2*m+1]);
                    acc[2*m+1] = fma2(rw1d, xb.y, acc[2*m+1]);
                }
                float ov[24];
                #pragma unroll
                for (int q = 0; q < 12; q++) {
                    float2 f = un2(acc[q]);
                    ov[2*q]   = fmaxf(f.x, 0.f);
                    ov[2*q+1] = fmaxf(f.y, 0.f);
                }
                ov[21] = 0.f; ov[22] = 0.f; ov[23] = 0.f;
                #pragma unroll
                for (int m = 0; m < 6; m++)
                    ((float4*)dst)[m] = make_float4(ov[4*m], ov[4*m+1], ov[4*m+2], ov[4*m+3]);
            }
        }
    }
    __syncthreads();

    // ---- stage D: folded tcn1, then in-reg A-mix + bias + res + relu ------
    const int s0loc = 2*wid;              // output slots s0loc, s0loc+1
    u64 acc0[12], acc1[12];
    #pragma unroll
    for (int q = 0; q < 12; q++) { acc0[q] = 0ull; acc1[q] = 0ull; }
    #pragma unroll 1
    for (int i = 0; i < NC; i++) {
        const float* wp = tw1s + i*3*NC + o;
        u64 w0 = dup2(wp[0]), w1 = dup2(wp[NC]), w2 = dup2(wp[2*NC]);
        #pragma unroll
        for (int r = 0; r < 4; r++) {
            const ulonglong2* rp = (const ulonglong2*)(bufH1 + ((size_t)(s0loc + r)*NC + i)*VP);
            u64 rr[12];
            #pragma unroll
            for (int m = 0; m < 6; m++) {
                ulonglong2 r2 = rp[m];
                rr[2*m] = r2.x; rr[2*m+1] = r2.y;
            }
            if (r < 3) {
                u64 w = (r == 0) ? w0 : (r == 1) ? w1 : w2;
                #pragma unroll
                for (int q = 0; q < 12; q++) acc0[q] = fma2(w, rr[q], acc0[q]);
            }
            if (r >= 1) {
                u64 w = (r == 1) ? w0 : (r == 2) ? w1 : w2;
                #pragma unroll
                for (int q = 0; q < 12; q++) acc1[q] = fma2(w, rr[q], acc1[q]);
            }
        }
    }

    float d0[24], d1[24];
    #pragma unroll
    for (int half = 0; half < 2; half++) {
        u64* acc = half ? acc1 : acc0;
        float* dq = half ? d1 : d0;
        int s = s0loc + half;
        int t = t0 + s;
        float qv[24];
        #pragma unroll
        for (int q = 0; q < 12; q++) {
            float2 f = un2(acc[q]);
            qv[2*q] = f.x; qv[2*q+1] = f.y;
        }
        float bias = pp[PP_TB1 + o] + pp[PP_BK1 + o] + pp[PP_BK1 + NC + o] + pp[PP_BK1 + 2*NC + o];
        if (t == 0)        bias -= pp[PP_BK1 + o];
        if (t == TLEN - 1) bias -= pp[PP_BK1 + 2*NC + o];
        float rres[24];
        const float4* rp4 = (const float4*)(bufH1 + ((size_t)(s + 1)*NC + o)*VP);
        #pragma unroll
        for (int m = 0; m < 6; m++) {
            float4 f = rp4[m];
            rres[4*m] = f.x; rres[4*m+1] = f.y; rres[4*m+2] = f.z; rres[4*m+3] = f.w;
        }
        #pragma unroll
        for (int v = 0; v < NV; v++) {
            float p = bias + rres[v];
            #pragma unroll
            for (int j = 0; j < 6; j++)
                if (j < DEG[v]) p += As[v*22 + NBR[v][j]] * qv[NBR[v][j]];
            dq[v] = fmaxf(p, 0.f);
        }
        dq[21] = 0.f; dq[22] = 0.f; dq[23] = 0.f;
    }
    __syncthreads();    // all bufH1 reads done -> reuse as hf[32][768]

    {
        float* h0 = bufH1 + (size_t)s0loc*FKP + o*VP;
        float* h1 = h0 + FKP;
        #pragma unroll
        for (int m = 0; m < 6; m++) {
            ((float4*)h0)[m] = make_float4(d0[4*m], d0[4*m+1], d0[4*m+2], d0[4*m+3]);
            ((float4*)h1)[m] = make_float4(d1[4*m], d1[4*m+1], d1[4*m+2], d1[4*m+3]);
        }
    }

    // ---- stage E: fc (768p -> 64), weights streamed through smem ----------
    {
        u64 a00 = 0ull, a01 = 0ull, a10 = 0ull, a11 = 0ull;
        const float* hA = bufH1 + (size_t)s0loc*FKP;
        const float* hB = hA + FKP;
        for (int c0 = 0; c0 < FKP; c0 += KC) {
            __syncthreads();   // protect fcs from prior-iter readers
            for (int i4 = tid; i4 < NOUT*(KC/4); i4 += NTHR) {
                int j = i4 >> 5, kk4 = i4 & 31;
                ((float4*)(fcs + j*KCP))[kk4] =
                    ((const float4*)(g_fcw2 + (size_t)j*FKP + c0))[kk4];
            }
            __syncthreads();
            const ulonglong2* wa4 = (const ulonglong2*)(fcs + lane*KCP);
            const ulonglong2* wb4 = (const ulonglong2*)(fcs + (lane + 32)*KCP);
            const ulonglong2* ha4 = (const ulonglong2*)(hA + c0);
            const ulonglong2* hb4 = (const ulonglong2*)(hB + c0);
            #pragma unroll
            for (int q = 0; q < KC/4; q++) {
                ulonglong2 wa = wa4[q], wb = wb4[q], ha = ha4[q], hb = hb4[q];
                a00 = fma2(wa.x, ha.x, a00);
                a01 = fma2(wb.x, ha.x, a01);
                a10 = fma2(wa.x, hb.x, a10);
                a11 = fma2(wb.x, hb.x, a11);
                a00 = fma2(wa.y, ha.y, a00);
                a01 = fma2(wb.y, ha.y, a01);
                a10 = fma2(wa.y, hb.y, a10);
                a11 = fma2(wb.y, hb.y, a11);
            }
        }
        int ta = t0 + s0loc, tb = ta + 1;
        float fb0 = pp[PP_FCB + lane], fb1 = pp[PP_FCB + lane + 32];
        float2 r;
        float* opa = outp + ((size_t)((b*TLEN + ta)*2 + hand))*NOUT;
        float* opb = outp + ((size_t)((b*TLEN + tb)*2 + hand))*NOUT;
        r = un2(a00); opa[lane]      = r.x + r.y + fb0;
        r = un2(a01); opa[lane + 32] = r.x + r.y + fb1;
        r = un2(a10); opb[lane]      = r.x + r.y + fb0;
        r = un2(a11); opb[lane + 32] = r.x + r.y + fb1;
    }
}

// ------------------------------- launch -------------------------------------
extern "C" void kernel_launch(void* const* d_in, const int* in_sizes, int n_in,
                              void* d_out, int out_size)
{
    (void)in_sizes; (void)n_in; (void)out_size;
    const float* x = (const float*)d_in[0];

    prep_kernel<<<48, 256>>>(
        (const float*)d_in[1],  (const float*)d_in[2],
        (const float*)d_in[3],  (const float*)d_in[4],
        (const float*)d_in[5],  (const float*)d_in[6],
        (const float*)d_in[7],  (const float*)d_in[8],
        (const float*)d_in[9],  (const float*)d_in[10],
        (const float*)d_in[11], (const float*)d_in[12],
        (const float*)d_in[13], (const float*)d_in[14],
        (const float*)d_in[15], (const float*)d_in[16],
        (const float*)d_in[17], (const float*)d_in[18],
        (const float*)d_in[19], (const float*)d_in[20],
        (const float*)d_in[21], (const float*)d_in[22],
        (const float*)d_in[23], (const float*)d_in[24]);

    cudaFuncSetAttribute(stgcn_kernel,
                         cudaFuncAttributeMaxDynamicSharedMemorySize, SMEM_BYTES);
    dim3 grid(NCHUNK, 2, 64);
    stgcn_kernel<<<grid, NTHR, SMEM_BYTES>>>(x, (float*)d_out);
}

// round 6
// speedup vs baseline: 1.1221x; 1.1221x over previous
#include <cuda_runtime.h>
#include <cstddef>

#define TLEN 512
#define NV 21
#define NC 32
#define TC 32
#define NTHR 512

// smem float offsets
#define OFF_R1 0           // Ht[32][820] (26240) ; later fcs[64][388] (24832)
#define OFF_R2 26240       // bufAx[36][48] ; later sc/hf[32][776] (24832)
#define OFF_XD 51072       // bufXd[36][48] (1728)
#define OFF_AS 52800       // A (464)
#define OFF_TW 53264       // tw1f (3072)
#define OFF_PP 56336       // pp (640)
#define SMEM_FLOATS 56976
#define SMEM_BYTES (SMEM_FLOATS*4)

#define PP_TW0 0
#define PP_BK0 192
#define PP_BK1 288
#define PP_TB0 384
#define PP_TB1 416
#define PP_RW 448
#define PP_RB 512
#define PP_FCB 544
#define PP_TOT 608

typedef unsigned long long u64;
__device__ __forceinline__ u64 fma2(u64 a,u64 b,u64 c){u64 d;asm("fma.rn.f32x2 %0,%1,%2,%3;":"=l"(d):"l"(a),"l"(b),"l"(c));return d;}
__device__ __forceinline__ u64 dup2(float v){u64 r;asm("mov.b64 %0,{%1,%1};":"=l"(r):"f"(v));return r;}
__device__ __forceinline__ float2 un2(u64 p){float2 f;asm("mov.b64 {%0,%1},%2;":"=f"(f.x),"=f"(f.y):"l"(p));return f;}

__device__ float g_A[464];
__device__ float g_tw1f[NC*3*NC];
__device__ float g_fcw2[64*768];
__device__ float g_pp[PP_TOT];

__global__ void prep_kernel(
    const float* __restrict__ gcn_w0,const float* __restrict__ gcn_b0,
    const float* __restrict__ tcn_w0,const float* __restrict__ tcn_b0,
    const float* __restrict__ bn_g0,const float* __restrict__ bn_b0,
    const float* __restrict__ bn_m0,const float* __restrict__ bn_v0,
    const float* __restrict__ res_w,const float* __restrict__ res_b,
    const float* __restrict__ res_bn_g,const float* __restrict__ res_bn_b,
    const float* __restrict__ res_bn_m,const float* __restrict__ res_bn_v,
    const float* __restrict__ gcn_w1,const float* __restrict__ gcn_b1,
    const float* __restrict__ tcn_w1,const float* __restrict__ tcn_b1,
    const float* __restrict__ bn_g1,const float* __restrict__ bn_b1,
    const float* __restrict__ bn_m1,const float* __restrict__ bn_v1,
    const float* __restrict__ fc_w,const float* __restrict__ fc_b)
{
    int gtid=blockIdx.x*blockDim.x+threadIdx.x, nthr=gridDim.x*blockDim.x;
    for(int idx=gtid;idx<64*768;idx+=nthr){
        int j=idx/768,kp=idx-j*768,c=kp/24,v=kp-c*24;
        g_fcw2[idx]=(v<NV)?fc_w[j*(NC*NV)+c*NV+v]:0.f;
    }
    for(int idx=gtid;idx<NC*3*NC;idx+=nthr){
        int o=idx&31,ik=idx>>5,i=ik/3,k=ik-i*3;
        float s1=bn_g1[o]*rsqrtf(bn_v1[o]+1e-5f),s=0.f;
        for(int j=0;j<NC;j++) s+=tcn_w1[(o*NC+j)*3+k]*gcn_w1[j*NC+i];
        g_tw1f[(i*3+k)*NC+o]=s*s1;
    }
    if(gtid==0){
        float Ad[NV][NV];
        for(int i=0;i<NV;i++)for(int j=0;j<NV;j++)Ad[i][j]=(i==j)?1.f:0.f;
        const int conn[20][2]={{0,1},{1,2},{2,3},{3,4},{0,5},{5,6},{6,7},{7,8},
            {0,9},{9,10},{10,11},{11,12},{0,13},{13,14},{14,15},{15,16},
            {0,17},{17,18},{18,19},{19,20}};
        for(int e=0;e<20;e++){Ad[conn[e][0]][conn[e][1]]=1.f;Ad[conn[e][1]][conn[e][0]]=1.f;}
        float d[NV];
        for(int i=0;i<NV;i++){float s=0.f;for(int j=0;j<NV;j++)s+=Ad[i][j];d[i]=rsqrtf(s);}
        for(int i=0;i<464;i++)g_A[i]=0.f;
        for(int i=0;i<NV;i++)for(int j=0;j<NV;j++)g_A[i*22+j]=d[i]*Ad[i][j]*d[j];
    }
    if(gtid<NC){
        int o=gtid;
        float s0=bn_g0[o]*rsqrtf(bn_v0[o]+1e-5f);
        float s1=bn_g1[o]*rsqrtf(bn_v1[o]+1e-5f);
        for(int k=0;k<3;k++){
            for(int ci=0;ci<2;ci++){
                float s=0.f;
                for(int i=0;i<NC;i++)s+=tcn_w0[(o*NC+i)*3+k]*gcn_w0[i*2+ci];
                g_pp[PP_TW0+(k*2+ci)*NC+o]=s*s0;
            }
            float sb=0.f;
            for(int i=0;i<NC;i++)sb+=tcn_w0[(o*NC+i)*3+k]*gcn_b0[i];
            g_pp[PP_BK0+k*NC+o]=sb*s0;
            float sb1=0.f;
            for(int j=0;j<NC;j++)sb1+=tcn_w1[(o*NC+j)*3+k]*gcn_b1[j];
            g_pp[PP_BK1+k*NC+o]=sb1*s1;
        }
        g_pp[PP_TB0+o]=(tcn_b0[o]-bn_m0[o])*s0+bn_b0[o];
        g_pp[PP_TB1+o]=(tcn_b1[o]-bn_m1[o])*s1+bn_b1[o];
        float sr=res_bn_g[o]*rsqrtf(res_bn_v[o]+1e-5f);
        g_pp[PP_RW+o]=res_w[o*2+0]*sr;
        g_pp[PP_RW+NC+o]=res_w[o*2+1]*sr;
        g_pp[PP_RB+o]=(res_b[o]-res_bn_m[o])*sr+res_bn_b[o];
    }
    if(gtid>=64&&gtid<128)g_pp[PP_FCB+gtid-64]=fc_b[gtid-64];
}

__global__ __launch_bounds__(NTHR,1)
void stgcn_kernel(const float* __restrict__ x,float* __restrict__ outp)
{
    extern __shared__ float smem[];
    float* R1=smem+OFF_R1;          // Ht / fcs
    float* R2=smem+OFF_R2;          // bufAx / sc(hf)
    float* bufXd=smem+OFF_XD;
    float* As=smem+OFF_AS;
    float* tws=smem+OFF_TW;
    float* pp=smem+OFF_PP;

    const int tid=threadIdx.x, lane=tid&31, wid=tid>>5;
    const int t0=blockIdx.x*TC, hand=blockIdx.y, b=blockIdx.z;

    constexpr int DEG[NV]={6,3,3,3,2,3,3,3,2,3,3,3,2,3,3,3,2,3,3,3,2};
    constexpr int NBR[NV][6]={
        {0,1,5,9,13,17},{0,1,2,0,0,0},{1,2,3,0,0,0},{2,3,4,0,0,0},{3,4,0,0,0,0},
        {0,5,6,0,0,0},{5,6,7,0,0,0},{6,7,8,0,0,0},{7,8,0,0,0,0},
        {0,9,10,0,0,0},{9,10,11,0,0,0},{10,11,12,0,0,0},{11,12,0,0,0,0},
        {0,13,14,0,0,0},{13,14,15,0,0,0},{14,15,16,0,0,0},{15,16,0,0,0,0},
        {0,17,18,0,0,0},{17,18,19,0,0,0},{18,19,20,0,0,0},{19,20,0,0,0,0}};

    // prolog
    for(int i=tid;i<464;i+=NTHR)As[i]=g_A[i];
    for(int i=tid;i<NC*3*NC;i+=NTHR)tws[i]=g_tw1f[i];
    for(int i=tid;i<PP_TOT;i+=NTHR)pp[i]=g_pp[i];

    // x fill: bufXd[s][ci*24+v], s=0..35, t=t0+s-2
    for(int idx=tid;idx<36*NV;idx+=NTHR){
        int s=idx/NV,v=idx-s*NV,t=t0+s-2;
        float2 xv=make_float2(0.f,0.f);
        if(t>=0&&t<TLEN)xv=*(const float2*)(x+(((size_t)(b*TLEN+t)*2+hand)*NV+v)*2);
        bufXd[s*48+v]=xv.x; bufXd[s*48+24+v]=xv.y;
    }
    __syncthreads();

    // stage A: A-mix -> bufAx (in R2)
    float* bufAx=R2;
    for(int sA=wid;sA<36;sA+=16){
        if(lane<24){
            float s0=0.f,s1=0.f;
            if(lane<NV){
                const float* Ar=As+lane*22; const float* xr=bufXd+sA*48;
                #pragma unroll
                for(int u=0;u<NV;u++){float a=Ar[u];s0+=a*xr[u];s1+=a*xr[24+u];}
            }
            bufAx[sA*48+lane]=s0; bufAx[sA*48+24+lane]=s1;
        }
    }
    __syncthreads();

    // stage B: folded tcn0+res+relu -> Ht[o][sB][24] (o-stride 820)
    {
        const int o=lane;
        const float bk00=pp[PP_BK0+o],bk02=pp[PP_BK0+64+o];
        const float biasAll=pp[PP_TB0+o]+bk00+pp[PP_BK0+32+o]+bk02+pp[PP_RB+o];
        const u64 rw0d=dup2(pp[PP_RW+o]),rw1d=dup2(pp[PP_RW+32+o]);
        for(int sB=wid;sB<34;sB+=16){
            int t=t0+sB-1;
            float* dst=R1+o*820+sB*24;
            if(t<0||t>=TLEN){
                float4 z=make_float4(0.f,0.f,0.f,0.f);
                #pragma unroll
                for(int m=0;m<6;m++)((float4*)dst)[m]=z;
            }else{
                float bias=biasAll;
                if(t==0)bias-=bk00;
                if(t==TLEN-1)bias-=bk02;
                u64 acc[12],bd=dup2(bias);
                #pragma unroll
                for(int q=0;q<12;q++)acc[q]=bd;
                #pragma unroll
                for(int k=0;k<3;k++)
                    #pragma unroll
                    for(int ci=0;ci<2;ci++){
                        u64 w=dup2(pp[PP_TW0+(k*2+ci)*NC+o]);
                        const ulonglong2* rp=(const ulonglong2*)(bufAx+(sB+k)*48+ci*24);
                        #pragma unroll
                        for(int m=0;m<6;m++){
                            ulonglong2 r2=rp[m];
                            acc[2*m]=fma2(w,r2.x,acc[2*m]);
                            acc[2*m+1]=fma2(w,r2.y,acc[2*m+1]);
                        }
                    }
                const ulonglong2* x0p=(const ulonglong2*)(bufXd+(sB+1)*48);
                const ulonglong2* x1p=(const ulonglong2*)(bufXd+(sB+1)*48+24);
                #pragma unroll
                for(int m=0;m<6;m++){
                    ulonglong2 xa=x0p[m],xb=x1p[m];
                    acc[2*m]=fma2(rw0d,xa.x,acc[2*m]);
                    acc[2*m]=fma2(rw1d,xb.x,acc[2*m]);
                    acc[2*m+1]=fma2(rw0d,xa.y,acc[2*m+1]);
                    acc[2*m+1]=fma2(rw1d,xb.y,acc[2*m+1]);
                }
                float ov[24];
                #pragma unroll
                for(int q=0;q<12;q++){float2 f=un2(acc[q]);ov[2*q]=fmaxf(f.x,0.f);ov[2*q+1]=fmaxf(f.y,0.f);}
                ov[21]=0.f;ov[22]=0.f;ov[23]=0.f;
                #pragma unroll
                for(int m=0;m<6;m++)((float4*)dst)[m]=make_float4(ov[4*m],ov[4*m+1],ov[4*m+2],ov[4*m+3]);
            }
        }
    }
    __syncthreads();

    // stage D (GEMM): raw[o][n] = sum_i,kt W[i,kt,o]*Ht[i][n+12kt], n=s*12+q
    // thread: og=tid>>7 (o=8og+oi), m=tid&127, n=m+128j (j=0..2)
    {
        const int og=tid>>7, m=tid&127;
        u64 acc[8][3];
        #pragma unroll
        for(int oi=0;oi<8;oi++)
            #pragma unroll
            for(int j=0;j<3;j++)acc[oi][j]=0ull;
        #pragma unroll 1
        for(int i=0;i<NC;i++){
            const float* wrow=tws+i*96+8*og;
            const float* hrow=R1+i*820+2*m;
            #pragma unroll
            for(int kt=0;kt<3;kt++){
                u64 h0=*(const u64*)(hrow+24*kt);
                u64 h1=*(const u64*)(hrow+256+24*kt);
                u64 h2=*(const u64*)(hrow+512+24*kt);
                float4 wa=*(const float4*)(wrow+kt*32);
                float4 wb=*(const float4*)(wrow+kt*32+4);
                u64 w0=dup2(wa.x),w1=dup2(wa.y),w2=dup2(wa.z),w3=dup2(wa.w);
                u64 w4=dup2(wb.x),w5=dup2(wb.y),w6=dup2(wb.z),w7=dup2(wb.w);
                acc[0][0]=fma2(w0,h0,acc[0][0]);acc[0][1]=fma2(w0,h1,acc[0][1]);acc[0][2]=fma2(w0,h2,acc[0][2]);
                acc[1][0]=fma2(w1,h0,acc[1][0]);acc[1][1]=fma2(w1,h1,acc[1][1]);acc[1][2]=fma2(w1,h2,acc[1][2]);
                acc[2][0]=fma2(w2,h0,acc[2][0]);acc[2][1]=fma2(w2,h1,acc[2][1]);acc[2][2]=fma2(w2,h2,acc[2][2]);
                acc[3][0]=fma2(w3,h0,acc[3][0]);acc[3][1]=fma2(w3,h1,acc[3][1]);acc[3][2]=fma2(w3,h2,acc[3][2]);
                acc[4][0]=fma2(w4,h0,acc[4][0]);acc[4][1]=fma2(w4,h1,acc[4][1]);acc[4][2]=fma2(w4,h2,acc[4][2]);
                acc[5][0]=fma2(w5,h0,acc[5][0]);acc[5][1]=fma2(w5,h1,acc[5][1]);acc[5][2]=fma2(w5,h2,acc[5][2]);
                acc[6][0]=fma2(w6,h0,acc[6][0]);acc[6][1]=fma2(w6,h1,acc[6][1]);acc[6][2]=fma2(w6,h2,acc[6][2]);
                acc[7][0]=fma2(w7,h0,acc[7][0]);acc[7][1]=fma2(w7,h1,acc[7][1]);acc[7][2]=fma2(w7,h2,acc[7][2]);
            }
        }
        __syncthreads();  // bufAx (R2) dead; sc goes into R2
        float* sc=R2;
        #pragma unroll
        for(int j=0;j<3;j++){
            int n=m+128*j, s=n/12, q=n-12*s;
            #pragma unroll
            for(int oi=0;oi<8;oi++)
                *(u64*)(sc+s*776+(8*og+oi)*24+2*q)=acc[oi][j];
        }
    }
    __syncthreads();

    // stage D2: A-mix + bias + res + relu, in place on sc
    {
        float* sc=R2;
        const int o=lane;
        const float bk10=pp[PP_BK1+o],bk12=pp[PP_BK1+64+o];
        const float biasAll=pp[PP_TB1+o]+bk10+pp[PP_BK1+32+o]+bk12;
        #pragma unroll
        for(int half=0;half<2;half++){
            int s=2*wid+half, t=t0+s;
            float* row=sc+s*776+o*24;
            float qv[24],rres[24];
            #pragma unroll
            for(int m=0;m<6;m++){
                float4 f=((const float4*)row)[m];
                qv[4*m]=f.x;qv[4*m+1]=f.y;qv[4*m+2]=f.z;qv[4*m+3]=f.w;
            }
            const float4* rp=(const float4*)(R1+o*820+(s+1)*24);
            #pragma unroll
            for(int m=0;m<6;m++){
                float4 f=rp[m];
                rres[4*m]=f.x;rres[4*m+1]=f.y;rres[4*m+2]=f.z;rres[4*m+3]=f.w;
            }
            float bias=biasAll;
            if(t==0)bias-=bk10;
            if(t==TLEN-1)bias-=bk12;
            float ov[24];
            #pragma unroll
            for(int v=0;v<NV;v++){
                float p=bias+rres[v];
                #pragma unroll
                for(int j=0;j<6;j++)
                    if(j<DEG[v])p+=As[v*22+NBR[v][j]]*qv[NBR[v][j]];
                ov[v]=fmaxf(p,0.f);
            }
            ov[21]=0.f;ov[22]=0.f;ov[23]=0.f;
            #pragma unroll
            for(int m=0;m<6;m++)((float4*)row)[m]=make_float4(ov[4*m],ov[4*m+1],ov[4*m+2],ov[4*m+3]);
        }
    }
    __syncthreads();

    // stage E: FC 768->64. hf = sc rows (776 stride). fcs chunks in R1.
    // warp w: slots 2w,2w+1. lane: kq=lane>>3, jg=lane&7. j = jg+8m (m=0..7).
    {
        float* hf=R2;
        float* fcs=R1;
        const int kq=lane>>3, jg=lane&7;
        const int sA=2*wid, sB=sA+1;
        u64 acc[8][2];
        #pragma unroll
        for(int m=0;m<8;m++){acc[m][0]=0ull;acc[m][1]=0ull;}
        for(int c=0;c<2;c++){
            __syncthreads();
            for(int i4=tid;i4<64*96;i4+=NTHR){
                int j=i4/96,kk=i4-j*96;
                ((float4*)(fcs+j*388))[kk]=((const float4*)(g_fcw2+(size_t)j*768+c*384))[kk];
            }
            __syncthreads();
            const int off0=kq*96;           // within-chunk float offset (quarter)
            const float* hrA=hf+sA*776+c*384+off0;
            const float* hrB=hf+sB*776+c*384+off0;
            #pragma unroll 4
            for(int it=0;it<24;it++){
                ulonglong2 ha=((const ulonglong2*)hrA)[it];
                ulonglong2 hb=((const ulonglong2*)hrB)[it];
                #pragma unroll
                for(int m=0;m<8;m++){
                    const ulonglong2 wv=*(const ulonglong2*)(fcs+(jg+8*m)*388+off0+4*it);
                    acc[m][0]=fma2(wv.x,ha.x,acc[m][0]);
                    acc[m][0]=fma2(wv.y,ha.y,acc[m][0]);
                    acc[m][1]=fma2(wv.x,hb.x,acc[m][1]);
                    acc[m][1]=fma2(wv.y,hb.y,acc[m][1]);
                }
            }
        }
        // reduce over kq (lane bits 3,4) and write
        float r[8][2];
        #pragma unroll
        for(int m=0;m<8;m++)
            #pragma unroll
            for(int sh=0;sh<2;sh++){
                float2 f=un2(acc[m][sh]);
                float v=f.x+f.y;
                v+=__shfl_xor_sync(0xffffffffu,v,8);
                v+=__shfl_xor_sync(0xffffffffu,v,16);
                r[m][sh]=v;
            }
        if(lane<8){
            int ta=t0+sA,tb=t0+sB;
            float* opa=outp+((size_t)((b*TLEN+ta)*2+hand))*64;
            float* opb=outp+((size_t)((b*TLEN+tb)*2+hand))*64;
            #pragma unroll
            for(int m=0;m<8;m++){
                int j=jg+8*m;
                float fb=pp[PP_FCB+j];
                opa[j]=r[m][0]+fb;
                opb[j]=r[m][1]+fb;
            }
        }
    }
}

extern "C" void kernel_launch(void* const* d_in,const int* in_sizes,int n_in,
                              void* d_out,int out_size)
{
    (void)in_sizes;(void)n_in;(void)out_size;
    prep_kernel<<<48,256>>>(
        (const float*)d_in[1],(const float*)d_in[2],(const float*)d_in[3],
        (const float*)d_in[4],(const float*)d_in[5],(const float*)d_in[6],
        (const float*)d_in[7],(const float*)d_in[8],(const float*)d_in[9],
        (const float*)d_in[10],(const float*)d_in[11],(const float*)d_in[12],
        (const float*)d_in[13],(const float*)d_in[14],(const float*)d_in[15],
        (const float*)d_in[16],(const float*)d_in[17],(const float*)d_in[18],
        (const float*)d_in[19],(const float*)d_in[20],(const float*)d_in[21],
        (const float*)d_in[22],(const float*)d_in[23],(const float*)d_in[24]);
    cudaFuncSetAttribute(stgcn_kernel,cudaFuncAttributeMaxDynamicSharedMemorySize,SMEM_BYTES);
    dim3 grid(16,2,64);
    stgcn_kernel<<<grid,NTHR,SMEM_BYTES>>>((const float*)d_in[0],(float*)d_out);
}

// round 7
// speedup vs baseline: 1.3562x; 1.2086x over previous
#include <cuda_runtime.h>
#include <cstddef>

#define TLEN 512
#define NV 21
#define NC 32
#define TC 32
#define NTHR 512

#define HT_S 820      // Ht row stride (205 units, 5 mod 8)
#define SC_S 772      // sc row stride (193 units, 1 mod 8)
#define FCS_S 388     // fcs row stride (97 units, 1 mod 8)

// smem float offsets
#define OFF_R1 0          // Ht[32][820]=26240 ; later fcs[64][388]=24832
#define OFF_R2 26240      // bufAx[36][48]=1728 ; later sc[32][772]=24704
#define OFF_XD 50944      // bufXd[36][48] (1728)
#define OFF_AS 52672      // A (464)
#define OFF_TW 53136      // tw1f (3072)
#define OFF_PP 56208      // pp (640)
#define SMEM_FLOATS 56848
#define SMEM_BYTES (SMEM_FLOATS*4)   // 227392 B

#define PP_TW0 0
#define PP_BK0 192
#define PP_BK1 288
#define PP_TB0 384
#define PP_TB1 416
#define PP_RW 448
#define PP_RB 512
#define PP_FCB 544
#define PP_TOT 608

typedef unsigned long long u64;
__device__ __forceinline__ u64 fma2(u64 a,u64 b,u64 c){u64 d;asm("fma.rn.f32x2 %0,%1,%2,%3;":"=l"(d):"l"(a),"l"(b),"l"(c));return d;}
__device__ __forceinline__ u64 dup2(float v){u64 r;asm("mov.b64 %0,{%1,%1};":"=l"(r):"f"(v));return r;}
__device__ __forceinline__ float2 un2(u64 p){float2 f;asm("mov.b64 {%0,%1},%2;":"=f"(f.x),"=f"(f.y):"l"(p));return f;}

__device__ float g_A[464];
__device__ float g_tw1f[NC*3*NC];
__device__ float g_fcw2[64*768];
__device__ float g_pp[PP_TOT];

__global__ void prep_kernel(
    const float* __restrict__ gcn_w0,const float* __restrict__ gcn_b0,
    const float* __restrict__ tcn_w0,const float* __restrict__ tcn_b0,
    const float* __restrict__ bn_g0,const float* __restrict__ bn_b0,
    const float* __restrict__ bn_m0,const float* __restrict__ bn_v0,
    const float* __restrict__ res_w,const float* __restrict__ res_b,
    const float* __restrict__ res_bn_g,const float* __restrict__ res_bn_b,
    const float* __restrict__ res_bn_m,const float* __restrict__ res_bn_v,
    const float* __restrict__ gcn_w1,const float* __restrict__ gcn_b1,
    const float* __restrict__ tcn_w1,const float* __restrict__ tcn_b1,
    const float* __restrict__ bn_g1,const float* __restrict__ bn_b1,
    const float* __restrict__ bn_m1,const float* __restrict__ bn_v1,
    const float* __restrict__ fc_w,const float* __restrict__ fc_b)
{
    int gtid=blockIdx.x*blockDim.x+threadIdx.x, nthr=gridDim.x*blockDim.x;
    for(int idx=gtid;idx<64*768;idx+=nthr){
        int j=idx/768,kp=idx-j*768,c=kp/24,v=kp-c*24;
        g_fcw2[idx]=(v<NV)?fc_w[j*(NC*NV)+c*NV+v]:0.f;
    }
    for(int idx=gtid;idx<NC*3*NC;idx+=nthr){
        int o=idx&31,ik=idx>>5,i=ik/3,k=ik-i*3;
        float s1=bn_g1[o]*rsqrtf(bn_v1[o]+1e-5f),s=0.f;
        for(int j=0;j<NC;j++) s+=tcn_w1[(o*NC+j)*3+k]*gcn_w1[j*NC+i];
        g_tw1f[(i*3+k)*NC+o]=s*s1;
    }
    if(gtid==0){
        float Ad[NV][NV];
        for(int i=0;i<NV;i++)for(int j=0;j<NV;j++)Ad[i][j]=(i==j)?1.f:0.f;
        const int conn[20][2]={{0,1},{1,2},{2,3},{3,4},{0,5},{5,6},{6,7},{7,8},
            {0,9},{9,10},{10,11},{11,12},{0,13},{13,14},{14,15},{15,16},
            {0,17},{17,18},{18,19},{19,20}};
        for(int e=0;e<20;e++){Ad[conn[e][0]][conn[e][1]]=1.f;Ad[conn[e][1]][conn[e][0]]=1.f;}
        float d[NV];
        for(int i=0;i<NV;i++){float s=0.f;for(int j=0;j<NV;j++)s+=Ad[i][j];d[i]=rsqrtf(s);}
        for(int i=0;i<464;i++)g_A[i]=0.f;
        for(int i=0;i<NV;i++)for(int j=0;j<NV;j++)g_A[i*22+j]=d[i]*Ad[i][j]*d[j];
    }
    if(gtid<NC){
        int o=gtid;
        float s0=bn_g0[o]*rsqrtf(bn_v0[o]+1e-5f);
        float s1=bn_g1[o]*rsqrtf(bn_v1[o]+1e-5f);
        for(int k=0;k<3;k++){
            for(int ci=0;ci<2;ci++){
                float s=0.f;
                for(int i=0;i<NC;i++)s+=tcn_w0[(o*NC+i)*3+k]*gcn_w0[i*2+ci];
                g_pp[PP_TW0+(k*2+ci)*NC+o]=s*s0;
            }
            float sb=0.f;
            for(int i=0;i<NC;i++)sb+=tcn_w0[(o*NC+i)*3+k]*gcn_b0[i];
            g_pp[PP_BK0+k*NC+o]=sb*s0;
            float sb1=0.f;
            for(int j=0;j<NC;j++)sb1+=tcn_w1[(o*NC+j)*3+k]*gcn_b1[j];
            g_pp[PP_BK1+k*NC+o]=sb1*s1;
        }
        g_pp[PP_TB0+o]=(tcn_b0[o]-bn_m0[o])*s0+bn_b0[o];
        g_pp[PP_TB1+o]=(tcn_b1[o]-bn_m1[o])*s1+bn_b1[o];
        float sr=res_bn_g[o]*rsqrtf(res_bn_v[o]+1e-5f);
        g_pp[PP_RW+o]=res_w[o*2+0]*sr;
        g_pp[PP_RW+NC+o]=res_w[o*2+1]*sr;
        g_pp[PP_RB+o]=(res_b[o]-res_bn_m[o])*sr+res_bn_b[o];
    }
    if(gtid>=64&&gtid<128)g_pp[PP_FCB+gtid-64]=fc_b[gtid-64];
}

__global__ __launch_bounds__(NTHR,1)
void stgcn_kernel(const float* __restrict__ x,float* __restrict__ outp)
{
    extern __shared__ float smem[];
    float* R1=smem+OFF_R1;          // Ht / fcs
    float* R2=smem+OFF_R2;          // bufAx / sc
    float* bufXd=smem+OFF_XD;
    float* As=smem+OFF_AS;
    float* tws=smem+OFF_TW;
    float* pp=smem+OFF_PP;

    const int tid=threadIdx.x, lane=tid&31, wid=tid>>5;
    const int t0=blockIdx.x*TC, hand=blockIdx.y, b=blockIdx.z;

    constexpr int DEG[NV]={6,3,3,3,2,3,3,3,2,3,3,3,2,3,3,3,2,3,3,3,2};
    constexpr int NBR[NV][6]={
        {0,1,5,9,13,17},{0,1,2,0,0,0},{1,2,3,0,0,0},{2,3,4,0,0,0},{3,4,0,0,0,0},
        {0,5,6,0,0,0},{5,6,7,0,0,0},{6,7,8,0,0,0},{7,8,0,0,0,0},
        {0,9,10,0,0,0},{9,10,11,0,0,0},{10,11,12,0,0,0},{11,12,0,0,0,0},
        {0,13,14,0,0,0},{13,14,15,0,0,0},{14,15,16,0,0,0},{15,16,0,0,0,0},
        {0,17,18,0,0,0},{17,18,19,0,0,0},{18,19,20,0,0,0},{19,20,0,0,0,0}};

    // prolog
    for(int i=tid;i<464;i+=NTHR)As[i]=g_A[i];
    for(int i=tid;i<NC*3*NC;i+=NTHR)tws[i]=g_tw1f[i];
    for(int i=tid;i<PP_TOT;i+=NTHR)pp[i]=g_pp[i];

    // x fill: bufXd[s][ci*24+v], s=0..35, t=t0+s-2
    for(int idx=tid;idx<36*NV;idx+=NTHR){
        int s=idx/NV,v=idx-s*NV,t=t0+s-2;
        float2 xv=make_float2(0.f,0.f);
        if(t>=0&&t<TLEN)xv=*(const float2*)(x+(((size_t)(b*TLEN+t)*2+hand)*NV+v)*2);
        bufXd[s*48+v]=xv.x; bufXd[s*48+24+v]=xv.y;
    }
    __syncthreads();

    // stage A: A-mix -> bufAx (in R2)
    float* bufAx=R2;
    for(int sA=wid;sA<36;sA+=16){
        if(lane<24){
            float s0=0.f,s1=0.f;
            if(lane<NV){
                const float* Ar=As+lane*22; const float* xr=bufXd+sA*48;
                #pragma unroll
                for(int u=0;u<NV;u++){float a=Ar[u];s0+=a*xr[u];s1+=a*xr[24+u];}
            }
            bufAx[sA*48+lane]=s0; bufAx[sA*48+24+lane]=s1;
        }
    }
    __syncthreads();

    // stage B: folded tcn0+res+relu -> Ht[o][sB*24+..]
    {
        const int o=lane;
        const float bk00=pp[PP_BK0+o],bk02=pp[PP_BK0+64+o];
        const float biasAll=pp[PP_TB0+o]+bk00+pp[PP_BK0+32+o]+bk02+pp[PP_RB+o];
        const u64 rw0d=dup2(pp[PP_RW+o]),rw1d=dup2(pp[PP_RW+32+o]);
        for(int sB=wid;sB<34;sB+=16){
            int t=t0+sB-1;
            float* dst=R1+o*HT_S+sB*24;
            if(t<0||t>=TLEN){
                float4 z=make_float4(0.f,0.f,0.f,0.f);
                #pragma unroll
                for(int m=0;m<6;m++)((float4*)dst)[m]=z;
            }else{
                float bias=biasAll;
                if(t==0)bias-=bk00;
                if(t==TLEN-1)bias-=bk02;
                u64 acc[12],bd=dup2(bias);
                #pragma unroll
                for(int q=0;q<12;q++)acc[q]=bd;
                #pragma unroll
                for(int k=0;k<3;k++)
                    #pragma unroll
                    for(int ci=0;ci<2;ci++){
                        u64 w=dup2(pp[PP_TW0+(k*2+ci)*NC+o]);
                        const ulonglong2* rp=(const ulonglong2*)(bufAx+(sB+k)*48+ci*24);
                        #pragma unroll
                        for(int m=0;m<6;m++){
                            ulonglong2 r2=rp[m];
                            acc[2*m]=fma2(w,r2.x,acc[2*m]);
                            acc[2*m+1]=fma2(w,r2.y,acc[2*m+1]);
                        }
                    }
                const ulonglong2* x0p=(const ulonglong2*)(bufXd+(sB+1)*48);
                const ulonglong2* x1p=(const ulonglong2*)(bufXd+(sB+1)*48+24);
                #pragma unroll
                for(int m=0;m<6;m++){
                    ulonglong2 xa=x0p[m],xb=x1p[m];
                    acc[2*m]=fma2(rw0d,xa.x,acc[2*m]);
                    acc[2*m]=fma2(rw1d,xb.x,acc[2*m]);
                    acc[2*m+1]=fma2(rw0d,xa.y,acc[2*m+1]);
                    acc[2*m+1]=fma2(rw1d,xb.y,acc[2*m+1]);
                }
                float ov[24];
                #pragma unroll
                for(int q=0;q<12;q++){float2 f=un2(acc[q]);ov[2*q]=fmaxf(f.x,0.f);ov[2*q+1]=fmaxf(f.y,0.f);}
                ov[21]=0.f;ov[22]=0.f;ov[23]=0.f;
                #pragma unroll
                for(int m=0;m<6;m++)((float4*)dst)[m]=make_float4(ov[4*m],ov[4*m+1],ov[4*m+2],ov[4*m+3]);
            }
        }
    }
    __syncthreads();   // bufAx dead from here; sc may be written

    // stage D (GEMM): raw[o][n] = sum_i,kt W[i,kt,o]*Ht[i][2n+24kt], n=s*12+q
    {
        const int og=tid>>7, m=tid&127;
        u64 acc[8][3];
        #pragma unroll
        for(int oi=0;oi<8;oi++)
            #pragma unroll
            for(int j=0;j<3;j++)acc[oi][j]=0ull;
        #pragma unroll 1
        for(int i=0;i<NC;i++){
            const float* wrow=tws+i*96+8*og;
            const float* hrow=R1+i*HT_S+2*m;
            #pragma unroll
            for(int kt=0;kt<3;kt++){
                u64 h0=*(const u64*)(hrow+24*kt);
                u64 h1=*(const u64*)(hrow+256+24*kt);
                u64 h2=*(const u64*)(hrow+512+24*kt);
                float4 wa=*(const float4*)(wrow+kt*32);
                float4 wb=*(const float4*)(wrow+kt*32+4);
                u64 w0=dup2(wa.x),w1=dup2(wa.y),w2=dup2(wa.z),w3=dup2(wa.w);
                u64 w4=dup2(wb.x),w5=dup2(wb.y),w6=dup2(wb.z),w7=dup2(wb.w);
                acc[0][0]=fma2(w0,h0,acc[0][0]);acc[0][1]=fma2(w0,h1,acc[0][1]);acc[0][2]=fma2(w0,h2,acc[0][2]);
                acc[1][0]=fma2(w1,h0,acc[1][0]);acc[1][1]=fma2(w1,h1,acc[1][1]);acc[1][2]=fma2(w1,h2,acc[1][2]);
                acc[2][0]=fma2(w2,h0,acc[2][0]);acc[2][1]=fma2(w2,h1,acc[2][1]);acc[2][2]=fma2(w2,h2,acc[2][2]);
                acc[3][0]=fma2(w3,h0,acc[3][0]);acc[3][1]=fma2(w3,h1,acc[3][1]);acc[3][2]=fma2(w3,h2,acc[3][2]);
                acc[4][0]=fma2(w4,h0,acc[4][0]);acc[4][1]=fma2(w4,h1,acc[4][1]);acc[4][2]=fma2(w4,h2,acc[4][2]);
                acc[5][0]=fma2(w5,h0,acc[5][0]);acc[5][1]=fma2(w5,h1,acc[5][1]);acc[5][2]=fma2(w5,h2,acc[5][2]);
                acc[6][0]=fma2(w6,h0,acc[6][0]);acc[6][1]=fma2(w6,h1,acc[6][1]);acc[6][2]=fma2(w6,h2,acc[6][2]);
                acc[7][0]=fma2(w7,h0,acc[7][0]);acc[7][1]=fma2(w7,h1,acc[7][1]);acc[7][2]=fma2(w7,h2,acc[7][2]);
            }
        }
        // scatter to sc (o-major, stride SC_S): col = 2n (linear in m -> coalesced)
        float* sc=R2;
        #pragma unroll
        for(int j=0;j<3;j++){
            int n=m+128*j;
            #pragma unroll
            for(int oi=0;oi<8;oi++)
                *(u64*)(sc+(8*og+oi)*SC_S+2*n)=acc[oi][j];
        }
    }
    __syncthreads();

    // stage D2: A-mix + bias + res + relu, in place on sc rows (o-major)
    {
        float* sc=R2;
        const int o=lane;
        const float bk10=pp[PP_BK1+o],bk12=pp[PP_BK1+64+o];
        const float biasAll=pp[PP_TB1+o]+bk10+pp[PP_BK1+32+o]+bk12;
        #pragma unroll
        for(int half=0;half<2;half++){
            int s=2*wid+half, t=t0+s;
            float* row=sc+o*SC_S+s*24;
            float qv[24],rres[24];
            #pragma unroll
            for(int m=0;m<6;m++){
                float4 f=((const float4*)row)[m];
                qv[4*m]=f.x;qv[4*m+1]=f.y;qv[4*m+2]=f.z;qv[4*m+3]=f.w;
            }
            const float4* rp=(const float4*)(R1+o*HT_S+(s+1)*24);
            #pragma unroll
            for(int m=0;m<6;m++){
                float4 f=rp[m];
                rres[4*m]=f.x;rres[4*m+1]=f.y;rres[4*m+2]=f.z;rres[4*m+3]=f.w;
            }
            float bias=biasAll;
            if(t==0)bias-=bk10;
            if(t==TLEN-1)bias-=bk12;
            float ov[24];
            #pragma unroll
            for(int v=0;v<NV;v++){
                float p=bias+rres[v];
                #pragma unroll
                for(int j=0;j<6;j++)
                    if(j<DEG[v])p+=As[v*22+NBR[v][j]]*qv[NBR[v][j]];
                ov[v]=fmaxf(p,0.f);
            }
            ov[21]=0.f;ov[22]=0.f;ov[23]=0.f;
            #pragma unroll
            for(int m=0;m<6;m++)((float4*)row)[m]=make_float4(ov[4*m],ov[4*m+1],ov[4*m+2],ov[4*m+3]);
        }
    }
    __syncthreads();   // Ht dead from here; fcs may overwrite R1

    // stage E: FC 768->64.
    // warp = (jh=wid&1, sg=wid>>1): 4 slots sbase..sbase+3, j in [32jh,32jh+32).
    // lane = (kq=lane>>3, jg=lane&7): j = 32jh+jg+8m (m=0..3); k-quarter = 4 o per chunk.
    // iteration rotation oi' = (oi+kq)&3 => conflict-free quads for both w and h.
    {
        float* sc=R2;
        float* fcs=R1;
        const int kq=lane>>3, jg=lane&7;
        const int jh=wid&1, sg=wid>>1;
        const int jbase=32*jh+jg;
        const int sbase=4*sg;
        u64 acc[4][4];
        #pragma unroll
        for(int m=0;m<4;m++)
            #pragma unroll
            for(int s=0;s<4;s++)acc[m][s]=0ull;

        #pragma unroll 1
        for(int c=0;c<2;c++){
            __syncthreads();
            for(int i4=tid;i4<64*96;i4+=NTHR){
                int j=i4/96,kk=i4-j*96;
                ((float4*)(fcs+j*FCS_S))[kk]=((const float4*)(g_fcw2+(size_t)j*768+c*384))[kk];
            }
            __syncthreads();
            #pragma unroll
            for(int oi=0;oi<4;oi++){
                const int oip=(oi+kq)&3;
                const int olocal=4*kq+oip;         // o_local within chunk (0..15)
                const int og=16*c+olocal;          // global o (0..31)
                const float* hbase=sc+og*SC_S;
                const float* wbase=fcs+olocal*24;
                #pragma unroll
                for(int vq=0;vq<6;vq++){
                    ulonglong2 h0=*(const ulonglong2*)(hbase+(sbase+0)*24+4*vq);
                    ulonglong2 h1=*(const ulonglong2*)(hbase+(sbase+1)*24+4*vq);
                    ulonglong2 h2=*(const ulonglong2*)(hbase+(sbase+2)*24+4*vq);
                    ulonglong2 h3=*(const ulonglong2*)(hbase+(sbase+3)*24+4*vq);
                    ulonglong2 w0=*(const ulonglong2*)(wbase+(jbase   )*FCS_S+4*vq);
                    ulonglong2 w1=*(const ulonglong2*)(wbase+(jbase+ 8)*FCS_S+4*vq);
                    ulonglong2 w2=*(const ulonglong2*)(wbase+(jbase+16)*FCS_S+4*vq);
                    ulonglong2 w3=*(const ulonglong2*)(wbase+(jbase+24)*FCS_S+4*vq);
                    acc[0][0]=fma2(w0.x,h0.x,acc[0][0]); acc[0][0]=fma2(w0.y,h0.y,acc[0][0]);
                    acc[0][1]=fma2(w0.x,h1.x,acc[0][1]); acc[0][1]=fma2(w0.y,h1.y,acc[0][1]);
                    acc[0][2]=fma2(w0.x,h2.x,acc[0][2]); acc[0][2]=fma2(w0.y,h2.y,acc[0][2]);
                    acc[0][3]=fma2(w0.x,h3.x,acc[0][3]); acc[0][3]=fma2(w0.y,h3.y,acc[0][3]);
                    acc[1][0]=fma2(w1.x,h0.x,acc[1][0]); acc[1][0]=fma2(w1.y,h0.y,acc[1][0]);
                    acc[1][1]=fma2(w1.x,h1.x,acc[1][1]); acc[1][1]=fma2(w1.y,h1.y,acc[1][1]);
                    acc[1][2]=fma2(w1.x,h2.x,acc[1][2]); acc[1][2]=fma2(w1.y,h2.y,acc[1][2]);
                    acc[1][3]=fma2(w1.x,h3.x,acc[1][3]); acc[1][3]=fma2(w1.y,h3.y,acc[1][3]);
                    acc[2][0]=fma2(w2.x,h0.x,acc[2][0]); acc[2][0]=fma2(w2.y,h0.y,acc[2][0]);
                    acc[2][1]=fma2(w2.x,h1.x,acc[2][1]); acc[2][1]=fma2(w2.y,h1.y,acc[2][1]);
                    acc[2][2]=fma2(w2.x,h2.x,acc[2][2]); acc[2][2]=fma2(w2.y,h2.y,acc[2][2]);
                    acc[2][3]=fma2(w2.x,h3.x,acc[2][3]); acc[2][3]=fma2(w2.y,h3.y,acc[2][3]);
                    acc[3][0]=fma2(w3.x,h0.x,acc[3][0]); acc[3][0]=fma2(w3.y,h0.y,acc[3][0]);
                    acc[3][1]=fma2(w3.x,h1.x,acc[3][1]); acc[3][1]=fma2(w3.y,h1.y,acc[3][1]);
                    acc[3][2]=fma2(w3.x,h2.x,acc[3][2]); acc[3][2]=fma2(w3.y,h2.y,acc[3][2]);
                    acc[3][3]=fma2(w3.x,h3.x,acc[3][3]); acc[3][3]=fma2(w3.y,h3.y,acc[3][3]);
                }
            }
        }
        // reduce over kq (lane bits 3,4), then lanes 0..7 write
        float r[4][4];
        #pragma unroll
        for(int m=0;m<4;m++)
            #pragma unroll
            for(int s=0;s<4;s++){
                float2 f=un2(acc[m][s]);
                float v=f.x+f.y;
                v+=__shfl_xor_sync(0xffffffffu,v,8);
                v+=__shfl_xor_sync(0xffffffffu,v,16);
                r[m][s]=v;
            }
        if(lane<8){
            #pragma unroll
            for(int s=0;s<4;s++){
                int t=t0+sbase+s;
                float* op=outp+((size_t)((b*TLEN+t)*2+hand))*64;
                #pragma unroll
                for(int m=0;m<4;m++){
                    int j=jbase+8*m;
                    op[j]=r[m][s]+pp[PP_FCB+j];
                }
            }
        }
    }
}

extern "C" void kernel_launch(void* const* d_in,const int* in_sizes,int n_in,
                              void* d_out,int out_size)
{
    (void)in_sizes;(void)n_in;(void)out_size;
    prep_kernel<<<48,256>>>(
        (const float*)d_in[1],(const float*)d_in[2],(const float*)d_in[3],
        (const float*)d_in[4],(const float*)d_in[5],(const float*)d_in[6],
        (const float*)d_in[7],(const float*)d_in[8],(const float*)d_in[9],
        (const float*)d_in[10],(const float*)d_in[11],(const float*)d_in[12],
        (const float*)d_in[13],(const float*)d_in[14],(const float*)d_in[15],
        (const float*)d_in[16],(const float*)d_in[17],(const float*)d_in[18],
        (const float*)d_in[19],(const float*)d_in[20],(const float*)d_in[21],
        (const float*)d_in[22],(const float*)d_in[23],(const float*)d_in[24]);
    cudaFuncSetAttribute(stgcn_kernel,cudaFuncAttributeMaxDynamicSharedMemorySize,SMEM_BYTES);
    dim3 grid(16,2,64);
    stgcn_kernel<<<grid,NTHR,SMEM_BYTES>>>((const float*)d_in[0],(float*)d_out);
}